// round 16
// baseline (speedup 1.0000x reference)
#include <cuda_runtime.h>
#include <cuda_bf16.h>
#include <cstdint>

typedef unsigned long long u64;

#define NP    64
#define NCOLS 500000
#define NT    128                       /* columns per gemm tile */
#define NB    ((NCOLS + NT - 1) / NT)   /* 3907 gemm blocks */
#define NANG  2016
#define NSEG  8
#define SEGL  (NANG / NSEG)             /* 252 */
#define XPITCH 132                      /* padded X row pitch (floats) */
#define NTHR  128
#define NWARP 4
#define DYN_BYTES 53248

// R as paired u64: d_Rh2[n*16 + kc*4 + lr] = {word(k2=kc*8+lr), word(k2+4)}
// word(k2) = {bf16 Rs[n][2k2] (lo half), bf16 Rs[n][2k2+1] (hi half)}
__device__ u64 d_Rh2[NP * 16];
__device__ u64 d_Rl2[NP * 16];
// segment products, ROW-major: d_SEG[b*4096 + i*64 + j] = S_b[i][j]
__device__ __align__(16) float d_SEG[NSEG * NP * NP];
__device__ int d_segdone = 0;
__device__ int d_flag    = 0;
__device__ int d_done    = 0;

// ---------------------------------------------------------------------------
// helpers
// ---------------------------------------------------------------------------
__device__ __forceinline__ void cpa16(uint32_t smem, const void* g) {
    asm volatile("cp.async.cg.shared.global [%0], [%1], 16;\n" :: "r"(smem), "l"(g));
}
__device__ __forceinline__ void cpa_commit() { asm volatile("cp.async.commit_group;\n"); }
template <int N> __device__ __forceinline__ void cpa_wait() {
    asm volatile("cp.async.wait_group %0;\n" :: "n"(N));
}
__device__ __forceinline__ uint32_t smem_u32(const void* p) {
    uint32_t a;
    asm("{ .reg .u64 t; cvta.to.shared.u64 t, %1; cvt.u32.u64 %0, t; }" : "=r"(a) : "l"(p));
    return a;
}
__device__ __forceinline__ void bsplit(float x0, float x1, uint32_t& hi, uint32_t& lo) {
    __nv_bfloat162 h = __floats2bfloat162_rn(x0, x1);       // .x = x0 (low half)
    hi = *reinterpret_cast<uint32_t*>(&h);
    __nv_bfloat162 l = __floats2bfloat162_rn(x0 - __bfloat162float(h.x),
                                             x1 - __bfloat162float(h.y));
    lo = *reinterpret_cast<uint32_t*>(&l);
}
__device__ __forceinline__ void mma16816(float* c, const uint32_t* a, const uint32_t* b) {
    asm volatile("mma.sync.aligned.m16n8k16.row.col.f32.bf16.bf16.f32 "
        "{%0,%1,%2,%3}, {%4,%5,%6,%7}, {%8,%9}, {%0,%1,%2,%3};"
        : "+f"(c[0]), "+f"(c[1]), "+f"(c[2]), "+f"(c[3])
        : "r"(a[0]), "r"(a[1]), "r"(a[2]), "r"(a[3]), "r"(b[0]), "r"(b[1]));
}

// ---------------------------------------------------------------------------
// ONE fused kernel, 128 threads/block.
//   blocks 0..7 : segment products (parallel); block 0: combine -> d_Rh2/d_Rl2
//   blocks 8..  : warp-AUTONOMOUS MMA pipelines (no __syncthreads in GEMM path)
// ---------------------------------------------------------------------------
__global__ void __launch_bounds__(NTHR, 4)
fused_kernel(const float* __restrict__ X,
             const float* __restrict__ angles,
             const float* __restrict__ mus,
             float* __restrict__ out) {
    extern __shared__ __align__(16) char dsm[];
    const uint32_t base = smem_u32(dsm);
    const int tid = threadIdx.x;

    // =======================================================================
    // Builder blocks (proven R13 path + paired-u64 split)
    // =======================================================================
    if (blockIdx.x < NSEG) {
        const int b = blockIdx.x;
        float2* cs = (float2*)dsm;                       // 252*8 B
        float*  M  = (float*)(dsm + 2048);               // 65 rows x 64 f

        for (int t = tid; t < SEGL; t += NTHR) {
            float s, c;
            sincosf(angles[b * SEGL + t], &s, &c);
            cs[t] = make_float2(c, s);
        }
        if (tid < NP) {
            #pragma unroll
            for (int i = 0; i < NP + 1; i++)
                M[i * NP + tid] = (i == tid) ? 1.0f : 0.0f;
        }
        __syncthreads();

        if (tid < NP) {
            const int j = tid;
            int it = 0, rem = b * SEGL;
            while (rem >= 63 - it) { rem -= 63 - it; it++; }
            int ib = it + 1 + rem;

            float* col = &M[j];
            float vt = col[it * NP];
            float mb = col[ib * NP];
            for (int t = 0; t < SEGL; t++) {
                int itn = it, ibn = ib + 1;
                if (ibn == NP) { itn = it + 1; ibn = itn + 1; }
                const float2 c_s = cs[t];
                const float  mbn = col[ibn * NP];
                const float  smb = c_s.y * mb;
                const float  cmb = c_s.x * mb;
                const float  nb  = fmaf(c_s.y, vt, cmb);
                const float  nvt = fmaf(c_s.x, vt, -smb);
                col[ib * NP] = nb;
                if (itn != it) {
                    col[it * NP] = nvt;
                    vt = col[itn * NP];
                    mb = col[ibn * NP];
                } else { vt = nvt; mb = mbn; }
                it = itn; ib = ibn;
            }
            col[it * NP] = vt;
        }
        __syncthreads();

        if (b != 0) {
            if (tid < NP) {
                float* Sg = d_SEG + b * (NP * NP);
                for (int i = 0; i < NP; i++)
                    Sg[i * NP + tid] = M[i * NP + tid];
            }
            __syncthreads();
            if (tid == 0) { __threadfence(); atomicAdd(&d_segdone, 1); }
            return;
        }

        // ---- block 0: combine P = S7*...*S0 (P0 = M rows 0..63 in place) ----
        if (tid == 0) {
            const volatile int* sd = &d_segdone;
            while (*sd < NSEG - 1) __nanosleep(64);
            __threadfence();
        }
        __syncthreads();

        float* P0  = (float*)(dsm + 2048);
        float* P1  = (float*)(dsm + 18432);
        float* Ssm = (float*)(dsm + 36864);
        const int j = tid & 63;
        const int q = tid >> 6;                          // 0..1, 32 rows each

        float* Pc = P0; float* Pd = P1;
        for (int s = 1; s < NSEG; s++) {
            const float4* Sg4 = (const float4*)(d_SEG + s * (NP * NP));
            float4* Ss4 = (float4*)Ssm;
            for (int t = tid; t < NP * NP / 4; t += NTHR) Ss4[t] = Sg4[t];
            __syncthreads();

            float acc[32];
            #pragma unroll
            for (int il = 0; il < 32; il++) acc[il] = 0.0f;
            #pragma unroll 4
            for (int k4 = 0; k4 < 16; k4++) {
                const float bv0 = Pc[(k4 * 4 + 0) * NP + j];
                const float bv1 = Pc[(k4 * 4 + 1) * NP + j];
                const float bv2 = Pc[(k4 * 4 + 2) * NP + j];
                const float bv3 = Pc[(k4 * 4 + 3) * NP + j];
                #pragma unroll
                for (int il = 0; il < 32; il++) {
                    const float4 s4 = *(const float4*)&Ssm[(q * 32 + il) * NP + k4 * 4];
                    acc[il] = fmaf(s4.x, bv0, fmaf(s4.y, bv1,
                              fmaf(s4.z, bv2, fmaf(s4.w, bv3, acc[il]))));
                }
            }
            __syncthreads();
            #pragma unroll
            for (int il = 0; il < 32; il++)
                Pd[(q * 32 + il) * NP + j] = acc[il];
            __syncthreads();
            float* tmp = Pc; Pc = Pd; Pd = tmp;
        }
        // split into paired-u64 bf16 hi/lo: index t = n*16 + kc*4 + lr
        for (int t = tid; t < NP * 16; t += NTHR) {
            const int n   = t >> 4;
            const int k2a = ((t >> 2) & 3) * 8 + (t & 3);    // kc*8 + lr
            const int k2b = k2a + 4;
            const float m = mus[n];
            uint32_t wah, wal, wbh, wbl;
            bsplit(Pc[n * NP + 2 * k2a] * m, Pc[n * NP + 2 * k2a + 1] * m, wah, wal);
            bsplit(Pc[n * NP + 2 * k2b] * m, Pc[n * NP + 2 * k2b + 1] * m, wbh, wbl);
            d_Rh2[t] = (u64)wah | ((u64)wbh << 32);
            d_Rl2[t] = (u64)wal | ((u64)wbl << 32);
        }
        __syncthreads();
        if (tid == 0) {
            d_segdone = 0;
            __threadfence();
            atomicExch(&d_flag, 1);
        }
        return;
    }

    // =======================================================================
    // GEMM blocks: 4 autonomous warps; warp w -> output cols col0 + w*32..+31
    // =======================================================================
    float* sXf = (float*)dsm;                             // [64][132] fp32

    const int col0 = (blockIdx.x - NSEG) * NT;
    const int w  = tid >> 5;
    const int l  = tid & 31;
    const int lq = l >> 2;
    const int lr = l & 3;

    // 1. stage THIS WARP's X chunk (64 rows x 32 cols) via cp.async
    {
        const int cbase = w * 32 + (l & 7) * 4;           // smem col offset
        const int gc    = min(col0 + cbase, NCOLS - 4);   // clamped global col
        const uint32_t dst0 = base + cbase * 4;
        const int rw = l >> 3;                            // 0..3
        #pragma unroll
        for (int p = 0; p < 16; p++) {
            const int row = p * 4 + rw;
            cpa16(dst0 + row * (XPITCH * 4), X + (size_t)row * NCOLS + gc);
        }
        cpa_commit();
    }

    // 2. per-warp wait for R (overlaps cp.async in flight)
    if (l == 0) {
        const volatile int* f = &d_flag;
        while (*f == 0) __nanosleep(256);
        __threadfence();
        if (atomicAdd(&d_done, 1) == NB * NWARP - 1) {    // last warp past spin
            d_done = 0;
            d_flag = 0;
        }
    }
    __syncwarp();

    // 3. own chunk resident
    cpa_wait<0>();
    __syncwarp();

    // 4. warp-MMA (R13 shape), B fragments via LDG.64 (L1-resident, 16 KB)
    float acc[2][8][4];
    #pragma unroll
    for (int mf = 0; mf < 2; mf++)
        #pragma unroll
        for (int nf = 0; nf < 8; nf++)
            #pragma unroll
            for (int r = 0; r < 4; r++) acc[mf][nf][r] = 0.0f;

    #pragma unroll
    for (int kc = 0; kc < 4; kc++) {
        // A fragments (hi+lo) from fp32 smem (conflict-free)
        uint32_t ahi[2][4], alo[2][4];
        #pragma unroll
        for (int mf = 0; mf < 2; mf++) {
            const int m0 = w * 32 + mf * 16 + lq;
            #pragma unroll
            for (int half = 0; half < 2; half++) {
                const int k2 = kc * 8 + lr + half * 4;
                const float* r0 = &sXf[(2 * k2) * XPITCH];
                const float* r1 = &sXf[(2 * k2 + 1) * XPITCH];
                bsplit(r0[m0],     r1[m0],     ahi[mf][half * 2 + 0], alo[mf][half * 2 + 0]);
                bsplit(r0[m0 + 8], r1[m0 + 8], ahi[mf][half * 2 + 1], alo[mf][half * 2 + 1]);
            }
        }
        // B fragments: ONE LDG.64 each; two groups of 4 nf
        #pragma unroll
        for (int nh = 0; nh < 2; nh++) {
            uint32_t bh[4][2], bl[4][2];
            #pragma unroll
            for (int nfi = 0; nfi < 4; nfi++) {
                const int i0 = ((nh * 4 + nfi) * 8 + lq) * 16 + kc * 4 + lr;
                *(u64*)bh[nfi] = d_Rh2[i0];
                *(u64*)bl[nfi] = d_Rl2[i0];
            }
            #pragma unroll
            for (int mf = 0; mf < 2; mf++)
                #pragma unroll
                for (int nfi = 0; nfi < 4; nfi++) {
                    float* c = acc[mf][nh * 4 + nfi];
                    mma16816(c, ahi[mf], bh[nfi]);   // hi*hi
                    mma16816(c, ahi[mf], bl[nfi]);   // hi*lo
                    mma16816(c, alo[mf], bh[nfi]);   // lo*hi
                }
        }
    }

    // 5. store (R13 pattern)
    #pragma unroll
    for (int mf = 0; mf < 2; mf++) {
        const int mA = w * 32 + mf * 16 + lq;
        const int mB = mA + 8;
        const bool okA = (col0 + mA < NCOLS);
        const bool okB = (col0 + mB < NCOLS);
        float* opA = out + col0 + mA;
        float* opB = out + col0 + mB;
        #pragma unroll
        for (int nf = 0; nf < 8; nf++) {
            const int n0 = nf * 8 + lr * 2;
            const float* c = acc[mf][nf];
            if (okA) {
                opA[(size_t)n0 * NCOLS]       = c[0];
                opA[(size_t)(n0 + 1) * NCOLS] = c[1];
            }
            if (okB) {
                opB[(size_t)n0 * NCOLS]       = c[2];
                opB[(size_t)(n0 + 1) * NCOLS] = c[3];
            }
        }
    }
}

// ---------------------------------------------------------------------------
extern "C" void kernel_launch(void* const* d_in, const int* in_sizes, int n_in,
                              void* d_out, int out_size) {
    const float* X      = (const float*)d_in[0];
    const float* angles = (const float*)d_in[1];
    const float* mus    = (const float*)d_in[2];
    float*       out    = (float*)d_out;

    cudaFuncSetAttribute(fused_kernel,
                         cudaFuncAttributeMaxDynamicSharedMemorySize, DYN_BYTES);
    fused_kernel<<<NB + NSEG, NTHR, DYN_BYTES>>>(X, angles, mus, out);
}

// round 17
// speedup vs baseline: 1.2553x; 1.2553x over previous
#include <cuda_runtime.h>
#include <cuda_bf16.h>
#include <cstdint>

#define NP    64
#define NCOLS 500000
#define NT    128                       /* columns per gemm tile */
#define NTILE ((NCOLS + NT - 1) / NT)   /* 3907 tiles */
#define NBLK  288                       /* persistent gemm blocks (296 - 8) */
#define NANG  2016
#define NSEG  8
#define SEGL  (NANG / NSEG)             /* 252 */
#define XPITCH 132                      /* padded X row pitch (floats) */
#define RPITCH 36                       /* padded R row pitch (u32 pair-words) */
#define NTHR  128
#define XBUF_BYTES (64 * XPITCH * 4)    /* 33792 */
#define DYN_BYTES (2 * XBUF_BYTES + 2 * 64 * RPITCH * 4)   /* 86016 */

// R split into bf16 hi/lo pair-words: d_Rh[n*32+k2] = {Rs[n][2k2] lo, Rs[n][2k2+1] hi}
__device__ uint32_t d_Rh[NP * 32];
__device__ uint32_t d_Rl[NP * 32];
// segment products, ROW-major: d_SEG[b*4096 + i*64 + j] = S_b[i][j]
__device__ __align__(16) float d_SEG[NSEG * NP * NP];
__device__ int d_segdone = 0;
__device__ int d_flag    = 0;
__device__ int d_done    = 0;

// ---------------------------------------------------------------------------
// helpers
// ---------------------------------------------------------------------------
__device__ __forceinline__ void cpa16(uint32_t smem, const void* g) {
    asm volatile("cp.async.cg.shared.global [%0], [%1], 16;\n" :: "r"(smem), "l"(g));
}
__device__ __forceinline__ void cpa_commit() { asm volatile("cp.async.commit_group;\n"); }
template <int N> __device__ __forceinline__ void cpa_wait() {
    asm volatile("cp.async.wait_group %0;\n" :: "n"(N));
}
__device__ __forceinline__ uint32_t smem_u32(const void* p) {
    uint32_t a;
    asm("{ .reg .u64 t; cvta.to.shared.u64 t, %1; cvt.u32.u64 %0, t; }" : "=r"(a) : "l"(p));
    return a;
}
__device__ __forceinline__ void bsplit(float x0, float x1, uint32_t& hi, uint32_t& lo) {
    __nv_bfloat162 h = __floats2bfloat162_rn(x0, x1);       // .x = x0 (low half)
    hi = *reinterpret_cast<uint32_t*>(&h);
    __nv_bfloat162 l = __floats2bfloat162_rn(x0 - __bfloat162float(h.x),
                                             x1 - __bfloat162float(h.y));
    lo = *reinterpret_cast<uint32_t*>(&l);
}
__device__ __forceinline__ uint32_t bf2_bits(__nv_bfloat16 a, __nv_bfloat16 b) {
    __nv_bfloat162 h = __halves2bfloat162(a, b);            // a = low half
    return *reinterpret_cast<uint32_t*>(&h);
}
__device__ __forceinline__ void mma16816(float* c, const uint32_t* a, const uint32_t* b) {
    asm volatile("mma.sync.aligned.m16n8k16.row.col.f32.bf16.bf16.f32 "
        "{%0,%1,%2,%3}, {%4,%5,%6,%7}, {%8,%9}, {%0,%1,%2,%3};"
        : "+f"(c[0]), "+f"(c[1]), "+f"(c[2]), "+f"(c[3])
        : "r"(a[0]), "r"(a[1]), "r"(a[2]), "r"(a[3]), "r"(b[0]), "r"(b[1]));
}

// ---------------------------------------------------------------------------
// ONE fused kernel, 128 threads/block.
//   blocks 0..7 : segment products (parallel); block 0: combine -> d_Rh/d_Rl
//   blocks 8..  : PERSISTENT gemm blocks, double-buffered tile pipeline,
//                 each tile = the proven R13 warp-MMA shape
// ---------------------------------------------------------------------------
__global__ void __launch_bounds__(NTHR, 2)
fused_kernel(const float* __restrict__ X,
             const float* __restrict__ angles,
             const float* __restrict__ mus,
             float* __restrict__ out) {
    extern __shared__ __align__(16) char dsm[];
    const uint32_t base = smem_u32(dsm);
    const int tid = threadIdx.x;

    // =======================================================================
    // Builder blocks (proven path)
    // =======================================================================
    if (blockIdx.x < NSEG) {
        const int b = blockIdx.x;
        float2* cs = (float2*)dsm;                       // 252*8 B
        float*  M  = (float*)(dsm + 2048);               // 65 rows x 64 f

        for (int t = tid; t < SEGL; t += NTHR) {
            float s, c;
            sincosf(angles[b * SEGL + t], &s, &c);
            cs[t] = make_float2(c, s);
        }
        if (tid < NP) {
            #pragma unroll
            for (int i = 0; i < NP + 1; i++)
                M[i * NP + tid] = (i == tid) ? 1.0f : 0.0f;
        }
        __syncthreads();

        if (tid < NP) {
            const int j = tid;
            int it = 0, rem = b * SEGL;
            while (rem >= 63 - it) { rem -= 63 - it; it++; }
            int ib = it + 1 + rem;

            float* col = &M[j];
            float vt = col[it * NP];
            float mb = col[ib * NP];
            for (int t = 0; t < SEGL; t++) {
                int itn = it, ibn = ib + 1;
                if (ibn == NP) { itn = it + 1; ibn = itn + 1; }
                const float2 c_s = cs[t];
                const float  mbn = col[ibn * NP];
                const float  smb = c_s.y * mb;
                const float  cmb = c_s.x * mb;
                const float  nb  = fmaf(c_s.y, vt, cmb);
                const float  nvt = fmaf(c_s.x, vt, -smb);
                col[ib * NP] = nb;
                if (itn != it) {
                    col[it * NP] = nvt;
                    vt = col[itn * NP];
                    mb = col[ibn * NP];
                } else { vt = nvt; mb = mbn; }
                it = itn; ib = ibn;
            }
            col[it * NP] = vt;
        }
        __syncthreads();

        if (b != 0) {
            if (tid < NP) {
                float* Sg = d_SEG + b * (NP * NP);
                for (int i = 0; i < NP; i++)
                    Sg[i * NP + tid] = M[i * NP + tid];
            }
            __syncthreads();
            if (tid == 0) { __threadfence(); atomicAdd(&d_segdone, 1); }
            return;
        }

        // ---- block 0: combine P = S7*...*S0 (P0 = M rows 0..63 in place) ----
        if (tid == 0) {
            const volatile int* sd = &d_segdone;
            while (*sd < NSEG - 1) __nanosleep(64);
            __threadfence();
        }
        __syncthreads();

        float* P0  = (float*)(dsm + 2048);
        float* P1  = (float*)(dsm + 18432);
        float* Ssm = (float*)(dsm + 36864);
        const int j = tid & 63;
        const int q = tid >> 6;                          // 0..1, 32 rows each

        float* Pc = P0; float* Pd = P1;
        for (int s = 1; s < NSEG; s++) {
            const float4* Sg4 = (const float4*)(d_SEG + s * (NP * NP));
            float4* Ss4 = (float4*)Ssm;
            for (int t = tid; t < NP * NP / 4; t += NTHR) Ss4[t] = Sg4[t];
            __syncthreads();

            float acc[32];
            #pragma unroll
            for (int il = 0; il < 32; il++) acc[il] = 0.0f;
            #pragma unroll 4
            for (int k4 = 0; k4 < 16; k4++) {
                const float bv0 = Pc[(k4 * 4 + 0) * NP + j];
                const float bv1 = Pc[(k4 * 4 + 1) * NP + j];
                const float bv2 = Pc[(k4 * 4 + 2) * NP + j];
                const float bv3 = Pc[(k4 * 4 + 3) * NP + j];
                #pragma unroll
                for (int il = 0; il < 32; il++) {
                    const float4 s4 = *(const float4*)&Ssm[(q * 32 + il) * NP + k4 * 4];
                    acc[il] = fmaf(s4.x, bv0, fmaf(s4.y, bv1,
                              fmaf(s4.z, bv2, fmaf(s4.w, bv3, acc[il]))));
                }
            }
            __syncthreads();
            #pragma unroll
            for (int il = 0; il < 32; il++)
                Pd[(q * 32 + il) * NP + j] = acc[il];
            __syncthreads();
            float* tmp = Pc; Pc = Pd; Pd = tmp;
        }
        // split Rs[n][k] = Pc[n*64+k]*mus[n] into bf16 hi/lo pair-words
        for (int t = tid; t < NP * 32; t += NTHR) {
            const int n = t >> 5, k2 = t & 31;
            const float m = mus[n];
            const float v0 = Pc[n * NP + 2 * k2]     * m;
            const float v1 = Pc[n * NP + 2 * k2 + 1] * m;
            const __nv_bfloat16 h0 = __float2bfloat16(v0);
            const __nv_bfloat16 h1 = __float2bfloat16(v1);
            d_Rh[t] = bf2_bits(h0, h1);
            d_Rl[t] = bf2_bits(__float2bfloat16(v0 - __bfloat162float(h0)),
                               __float2bfloat16(v1 - __bfloat162float(h1)));
        }
        __syncthreads();
        if (tid == 0) {
            d_segdone = 0;
            __threadfence();
            atomicExch(&d_flag, 1);
        }
        return;
    }

    // =======================================================================
    // Persistent GEMM blocks: tiles pid, pid+NBLK, ... double-buffered
    // =======================================================================
    const int pid = blockIdx.x - NSEG;
    uint32_t* sRh = (uint32_t*)(dsm + 2 * XBUF_BYTES);    // [64][36]
    uint32_t* sRl = (uint32_t*)(dsm + 2 * XBUF_BYTES + 64 * RPITCH * 4);

    const int w  = tid >> 5;
    const int l  = tid & 31;
    const int lq = l >> 2;
    const int lr = l & 3;

    // per-thread cp.async slot: row = tid>>5 + 4p... use R13 mapping
    const int xrow = tid >> 5;            // via p loop: row = p*4 + (tid>>5) NO —
    // R13 mapping: idx = p*128 + tid; row = idx>>5 = p*4 + (tid>>5); seg = tid&31
    const int xseg = tid & 31;

    // prologue: load tiles pid (buf0) and pid+NBLK (buf1)
    #pragma unroll 1
    for (int pre = 0; pre < 2; pre++) {
        const int tile = pid + pre * NBLK;
        if (tile < NTILE) {
            const int ct = tile * NT;
            const int c  = min(ct + xseg * 4, NCOLS - 4);
            const uint32_t dst = base + pre * XBUF_BYTES + xseg * 16;
            #pragma unroll
            for (int p = 0; p < 16; p++) {
                const int row = p * 4 + xrow;
                cpa16(dst + row * (XPITCH * 4), X + (size_t)row * NCOLS + c);
            }
        }
        cpa_commit();
    }

    // wait for R (overlaps prologue loads)
    if (tid == 0) {
        const volatile int* f = &d_flag;
        while (*f == 0) __nanosleep(256);
        __threadfence();
        if (atomicAdd(&d_done, 1) == NBLK - 1) { d_done = 0; d_flag = 0; }
    }
    __syncthreads();

    // stage R once per block (R13 conflict-free layout)
    #pragma unroll
    for (int p = 0; p < 16; p++) {
        const int t = p * NTHR + tid;                // 0..2047
        const int n = t >> 5, k2 = t & 31;
        sRh[n * RPITCH + k2] = d_Rh[t];
        sRl[n * RPITCH + k2] = d_Rl[t];
    }
    // no extra barrier: the loop-top __syncthreads covers sR visibility

    #pragma unroll 1
    for (int i = 0; ; i++) {
        const int tile = pid + i * NBLK;
        if (tile >= NTILE) break;
        const int buf  = i & 1;
        const int col0 = tile * NT;

        cpa_wait<1>();          // tile i resident (newest group may be pending)
        __syncthreads();

        const float* sXf = (const float*)(dsm + buf * XBUF_BYTES);

        // ---- R13 warp-MMA tile ----
        float acc[2][8][4];
        #pragma unroll
        for (int mf = 0; mf < 2; mf++)
            #pragma unroll
            for (int nf = 0; nf < 8; nf++)
                #pragma unroll
                for (int r = 0; r < 4; r++) acc[mf][nf][r] = 0.0f;

        #pragma unroll
        for (int kc = 0; kc < 4; kc++) {
            uint32_t ahi[2][4], alo[2][4];
            #pragma unroll
            for (int mf = 0; mf < 2; mf++) {
                const int m0 = w * 32 + mf * 16 + lq;
                #pragma unroll
                for (int half = 0; half < 2; half++) {
                    const int k2 = kc * 8 + lr + half * 4;
                    const float* r0 = &sXf[(2 * k2) * XPITCH];
                    const float* r1 = &sXf[(2 * k2 + 1) * XPITCH];
                    bsplit(r0[m0],     r1[m0],     ahi[mf][half * 2 + 0], alo[mf][half * 2 + 0]);
                    bsplit(r0[m0 + 8], r1[m0 + 8], ahi[mf][half * 2 + 1], alo[mf][half * 2 + 1]);
                }
            }
            #pragma unroll
            for (int nh = 0; nh < 2; nh++) {
                uint32_t bh[4][2], bl[4][2];
                #pragma unroll
                for (int nfi = 0; nfi < 4; nfi++) {
                    const int n  = (nh * 4 + nfi) * 8 + lq;
                    const int i0 = n * RPITCH + kc * 8 + lr;
                    bh[nfi][0] = sRh[i0];     bh[nfi][1] = sRh[i0 + 4];
                    bl[nfi][0] = sRl[i0];     bl[nfi][1] = sRl[i0 + 4];
                }
                #pragma unroll
                for (int mf = 0; mf < 2; mf++)
                    #pragma unroll
                    for (int nfi = 0; nfi < 4; nfi++) {
                        float* c = acc[mf][nh * 4 + nfi];
                        mma16816(c, ahi[mf], bh[nfi]);   // hi*hi
                        mma16816(c, ahi[mf], bl[nfi]);   // hi*lo
                        mma16816(c, alo[mf], bh[nfi]);   // lo*hi
                    }
            }
        }

        __syncthreads();        // all warps done reading buf before refill

        // refill this buffer with tile i+2 (overlaps the stores below)
        {
            const int ntile = pid + (i + 2) * NBLK;
            if (ntile < NTILE) {
                const int ct = ntile * NT;
                const int c  = min(ct + xseg * 4, NCOLS - 4);
                const uint32_t dst = base + buf * XBUF_BYTES + xseg * 16;
                #pragma unroll
                for (int p = 0; p < 16; p++) {
                    const int row = p * 4 + xrow;
                    cpa16(dst + row * (XPITCH * 4), X + (size_t)row * NCOLS + c);
                }
            }
            cpa_commit();
        }

        // ---- store (R13 pattern) ----
        #pragma unroll
        for (int mf = 0; mf < 2; mf++) {
            const int mA = w * 32 + mf * 16 + lq;
            const int mB = mA + 8;
            const bool okA = (col0 + mA < NCOLS);
            const bool okB = (col0 + mB < NCOLS);
            float* opA = out + col0 + mA;
            float* opB = out + col0 + mB;
            #pragma unroll
            for (int nf = 0; nf < 8; nf++) {
                const int n0 = nf * 8 + lr * 2;
                const float* c = acc[mf][nf];
                if (okA) {
                    opA[(size_t)n0 * NCOLS]       = c[0];
                    opA[(size_t)(n0 + 1) * NCOLS] = c[1];
                }
                if (okB) {
                    opB[(size_t)n0 * NCOLS]       = c[2];
                    opB[(size_t)(n0 + 1) * NCOLS] = c[3];
                }
            }
        }
    }
}

// ---------------------------------------------------------------------------
extern "C" void kernel_launch(void* const* d_in, const int* in_sizes, int n_in,
                              void* d_out, int out_size) {
    const float* X      = (const float*)d_in[0];
    const float* angles = (const float*)d_in[1];
    const float* mus    = (const float*)d_in[2];
    float*       out    = (float*)d_out;

    cudaFuncSetAttribute(fused_kernel,
                         cudaFuncAttributeMaxDynamicSharedMemorySize, DYN_BYTES);
    fused_kernel<<<NBLK + NSEG, NTHR, DYN_BYTES>>>(X, angles, mus, out);
}